// round 1
// baseline (speedup 1.0000x reference)
#include <cuda_runtime.h>

// Fused Quanvolution-Hybrid:
//   conv(2x2, stride2) -> 4-qubit circuit (analytic closed form) -> FC(784->10) -> log_softmax
//
// Closed form of the quantum filter (Heisenberg-picture conjugation of Z_w
// through CNOT(0,1),CNOT(1,2),CNOT(2,3),RY(a4,0); learned RYs on wires 0-3 fold
// into the encoding angles):
//   theta_w = conv_out_w + angles[w],  c_w = cos(theta_w), s_w = sin(theta_w)
//   <Z0> = cos(a4)*c0 - sin(a4)*s0*s1
//   <Z1> = c0*c1
//   <Z2> = c0*c1*c2
//   <Z3> = c0*c1*c2*c3

#define G_IMGS 4          // images per block
#define TPB    224        // 7 warps; threads [0,196) map to 14x14 patches
#define NW     7

__global__ __launch_bounds__(TPB) void quanv_fused(
    const float* __restrict__ x,        // [B,1,28,28]
    const float* __restrict__ conv_w,   // [4,1,2,2]
    const float* __restrict__ conv_b,   // [4]
    const float* __restrict__ angles,   // [5]
    const float* __restrict__ fc_w,     // [10, 784]  (feature = c*196 + patch)
    const float* __restrict__ fc_b,     // [10]
    float* __restrict__ out,            // [B,10]
    int B)
{
    const int t    = threadIdx.x;
    const int lane = t & 31;
    const int warp = t >> 5;
    const int b0   = blockIdx.x * G_IMGS;

    __shared__ float s_part[G_IMGS][NW][10];
    __shared__ float s_logits[G_IMGS][10];

    // Uniform parameters (broadcast LDGs, L1-cached)
    float w00[4], w01[4], w10[4], w11[4], bb[4];
#pragma unroll
    for (int c = 0; c < 4; c++) {
        w00[c] = conv_w[c * 4 + 0];
        w01[c] = conv_w[c * 4 + 1];
        w10[c] = conv_w[c * 4 + 2];
        w11[c] = conv_w[c * 4 + 3];
        bb[c]  = conv_b[c] + angles[c];  // fold learned RY angle into encoding
    }
    float sa4, ca4;
    __sincosf(angles[4], &sa4, &ca4);

    const bool active = (t < 196);

    // Per-thread FC weight slice: fw[c][o] = fc_w[o*784 + c*196 + t]
    float fw[4][10];
#pragma unroll
    for (int c = 0; c < 4; c++) {
#pragma unroll
        for (int o = 0; o < 10; o++)
            fw[c][o] = active ? fc_w[o * 784 + c * 196 + t] : 0.0f;
    }

    const int h    = t / 14;
    const int wq   = t - h * 14;
    const int poff = (2 * h) * 28 + 2 * wq;   // even -> 8B aligned for float2

#pragma unroll
    for (int g = 0; g < G_IMGS; g++) {
        float acc[10];
#pragma unroll
        for (int o = 0; o < 10; o++) acc[o] = 0.0f;

        const int b = b0 + g;
        if (active && b < B) {
            const float* xb = x + (size_t)b * 784 + poff;
            float2 p0 = *reinterpret_cast<const float2*>(xb);
            float2 p1 = *reinterpret_cast<const float2*>(xb + 28);

            float th[4];
#pragma unroll
            for (int c = 0; c < 4; c++)
                th[c] = fmaf(p0.x, w00[c],
                        fmaf(p0.y, w01[c],
                        fmaf(p1.x, w10[c],
                        fmaf(p1.y, w11[c], bb[c]))));

            float s0, c0, s1, c1;
            __sincosf(th[0], &s0, &c0);
            __sincosf(th[1], &s1, &c1);
            const float c2 = __cosf(th[2]);
            const float c3 = __cosf(th[3]);

            const float ez0 = fmaf(ca4, c0, -sa4 * s0 * s1);
            const float ez1 = c0 * c1;
            const float ez2 = ez1 * c2;
            const float ez3 = ez2 * c3;

#pragma unroll
            for (int o = 0; o < 10; o++)
                acc[o] = fmaf(ez0, fw[0][o],
                         fmaf(ez1, fw[1][o],
                         fmaf(ez2, fw[2][o], ez3 * fw[3][o])));
        }

        // Deterministic warp tree-reduce of the 10 partial logits
#pragma unroll
        for (int off = 16; off > 0; off >>= 1) {
#pragma unroll
            for (int o = 0; o < 10; o++)
                acc[o] += __shfl_down_sync(0xffffffffu, acc[o], off);
        }
        if (lane == 0) {
#pragma unroll
            for (int o = 0; o < 10; o++)
                s_part[g][warp][o] = acc[o];
        }
    }
    __syncthreads();

    // Cross-warp reduce: one thread per (image, class)
    if (t < G_IMGS * 10) {
        const int g = t / 10, o = t - g * 10;
        float v = fc_b[o];
#pragma unroll
        for (int k = 0; k < NW; k++) v += s_part[g][k][o];
        s_logits[g][o] = v;
    }
    __syncthreads();

    // log_softmax over 10 classes (redundant per-thread lse, trivially cheap)
    if (t < G_IMGS * 10) {
        const int g = t / 10, o = t - g * 10;
        const int b = b0 + g;
        if (b < B) {
            float m = -1e30f;
#pragma unroll
            for (int j = 0; j < 10; j++) m = fmaxf(m, s_logits[g][j]);
            float se = 0.0f;
#pragma unroll
            for (int j = 0; j < 10; j++) se += __expf(s_logits[g][j] - m);
            out[b * 10 + o] = s_logits[g][o] - m - __logf(se);
        }
    }
}

extern "C" void kernel_launch(void* const* d_in, const int* in_sizes, int n_in,
                              void* d_out, int out_size)
{
    const float* x      = (const float*)d_in[0];
    const float* conv_w = (const float*)d_in[1];
    const float* conv_b = (const float*)d_in[2];
    const float* angles = (const float*)d_in[3];
    const float* fc_w   = (const float*)d_in[4];
    const float* fc_b   = (const float*)d_in[5];
    float* out = (float*)d_out;

    const int B = in_sizes[0] / 784;                 // 4096
    const int blocks = (B + G_IMGS - 1) / G_IMGS;    // 1024

    quanv_fused<<<blocks, TPB>>>(x, conv_w, conv_b, angles, fc_w, fc_b, out, B);
}

// round 2
// speedup vs baseline: 1.4837x; 1.4837x over previous
#include <cuda_runtime.h>

// Fused Quanvolution-Hybrid (analytic 4-qubit circuit):
//   theta_w = conv_out_w + angles[w];  c_w=cos, s_w=sin
//   <Z0> = cos(a4)*c0 - sin(a4)*s0*s1
//   <Z1> = c0*c1,  <Z2> = c0*c1*c2,  <Z3> = c0*c1*c2*c3
// then FC(784->10) + log_softmax, all in one kernel.

#define G_IMGS 8          // images per block
#define TPB    224        // 7 warps; threads [0,196) map to 14x14 patches
#define NW     7
#define PSTRIDE 85        // 8*10 + 5 pad: lane stride 85 -> 16 distinct smem banks

__global__ __launch_bounds__(TPB) void quanv_fused(
    const float* __restrict__ x,        // [B,1,28,28]
    const float* __restrict__ conv_w,   // [4,1,2,2]
    const float* __restrict__ conv_b,   // [4]
    const float* __restrict__ angles,   // [5]
    const float* __restrict__ fc_w,     // [10, 784]
    const float* __restrict__ fc_b,     // [10]
    float* __restrict__ out,            // [B,10]
    int B)
{
    const int t    = threadIdx.x;
    const int lane = t & 31;
    const int warp = t >> 5;
    const int b0   = blockIdx.x * G_IMGS;

    // s_part[warp][halfLane][g*10+o] : per-warp 16 partial sums per (image,class)
    __shared__ float s_part[NW][16][PSTRIDE];
    __shared__ float s_logits[G_IMGS][10];

    // Uniform parameters (broadcast LDGs, L1-cached)
    float w00[4], w01[4], w10[4], w11[4], bb[4];
#pragma unroll
    for (int c = 0; c < 4; c++) {
        w00[c] = conv_w[c * 4 + 0];
        w01[c] = conv_w[c * 4 + 1];
        w10[c] = conv_w[c * 4 + 2];
        w11[c] = conv_w[c * 4 + 3];
        bb[c]  = conv_b[c] + angles[c];   // fold learned RY into encoding angle
    }
    float sa4, ca4;
    __sincosf(angles[4], &sa4, &ca4);

    const bool active = (t < 196);

    // Per-thread FC weight slice: fw[c][o] = fc_w[o*784 + c*196 + t]
    float fw[4][10];
#pragma unroll
    for (int c = 0; c < 4; c++) {
#pragma unroll
        for (int o = 0; o < 10; o++)
            fw[c][o] = active ? fc_w[o * 784 + c * 196 + t] : 0.0f;
    }

    const int h    = t / 14;
    const int wq   = t - h * 14;
    const int poff = (2 * h) * 28 + 2 * wq;   // even -> 8B aligned float2

#pragma unroll
    for (int g = 0; g < G_IMGS; g++) {
        float acc[10];
#pragma unroll
        for (int o = 0; o < 10; o++) acc[o] = 0.0f;

        const int b = b0 + g;
        if (active && b < B) {
            const float* xb = x + (size_t)b * 784 + poff;
            float2 p0 = *reinterpret_cast<const float2*>(xb);
            float2 p1 = *reinterpret_cast<const float2*>(xb + 28);

            float th[4];
#pragma unroll
            for (int c = 0; c < 4; c++)
                th[c] = fmaf(p0.x, w00[c],
                        fmaf(p0.y, w01[c],
                        fmaf(p1.x, w10[c],
                        fmaf(p1.y, w11[c], bb[c]))));

            float s0, c0, s1, c1;
            __sincosf(th[0], &s0, &c0);
            __sincosf(th[1], &s1, &c1);
            const float c2 = __cosf(th[2]);
            const float c3 = __cosf(th[3]);

            const float ez0 = fmaf(ca4, c0, -sa4 * s0 * s1);
            const float ez1 = c0 * c1;
            const float ez2 = ez1 * c2;
            const float ez3 = ez2 * c3;

#pragma unroll
            for (int o = 0; o < 10; o++)
                acc[o] = fmaf(ez0, fw[0][o],
                         fmaf(ez1, fw[1][o],
                         fmaf(ez2, fw[2][o], ez3 * fw[3][o])));
        }

        // 1-level reduce: lane i += lane i+16, then 16 partials -> shared
#pragma unroll
        for (int o = 0; o < 10; o++)
            acc[o] += __shfl_down_sync(0xffffffffu, acc[o], 16);

        if (lane < 16) {
#pragma unroll
            for (int o = 0; o < 10; o++)
                s_part[warp][lane][g * 10 + o] = acc[o];
        }
    }
    __syncthreads();

    // Tail: one thread per (image,class) sums 7*16 = 112 partials (conflict-free LDS)
    if (t < G_IMGS * 10) {
        const int g = t / 10, o = t - g * 10;
        float v0 = fc_b[o], v1 = 0.f, v2 = 0.f, v3 = 0.f;
#pragma unroll
        for (int k = 0; k < NW; k++) {
#pragma unroll
            for (int j = 0; j < 16; j += 4) {
                v0 += s_part[k][j + 0][t];
                v1 += s_part[k][j + 1][t];
                v2 += s_part[k][j + 2][t];
                v3 += s_part[k][j + 3][t];
            }
        }
        s_logits[g][o] = (v0 + v1) + (v2 + v3);
    }
    __syncthreads();

    // log_softmax over 10 classes (redundant per-thread lse, trivially cheap)
    if (t < G_IMGS * 10) {
        const int g = t / 10, o = t - g * 10;
        const int b = b0 + g;
        if (b < B) {
            float m = -1e30f;
#pragma unroll
            for (int j = 0; j < 10; j++) m = fmaxf(m, s_logits[g][j]);
            float se = 0.0f;
#pragma unroll
            for (int j = 0; j < 10; j++) se += __expf(s_logits[g][j] - m);
            out[b * 10 + o] = s_logits[g][o] - m - __logf(se);
        }
    }
}

extern "C" void kernel_launch(void* const* d_in, const int* in_sizes, int n_in,
                              void* d_out, int out_size)
{
    const float* x      = (const float*)d_in[0];
    const float* conv_w = (const float*)d_in[1];
    const float* conv_b = (const float*)d_in[2];
    const float* angles = (const float*)d_in[3];
    const float* fc_w   = (const float*)d_in[4];
    const float* fc_b   = (const float*)d_in[5];
    float* out = (float*)d_out;

    const int B = in_sizes[0] / 784;                 // 4096
    const int blocks = (B + G_IMGS - 1) / G_IMGS;    // 512

    quanv_fused<<<blocks, TPB>>>(x, conv_w, conv_b, angles, fc_w, fc_b, out, B);
}

// round 3
// speedup vs baseline: 1.4987x; 1.0101x over previous
#include <cuda_runtime.h>

// Fused Quanvolution-Hybrid (analytic 4-qubit circuit), packed-f32x2 edition.
//   theta_w = conv_out_w + angles[w];  c_w=cos, s_w=sin
//   <Z0> = cos(a4)*c0 - sin(a4)*s0*s1
//   <Z1> = c0*c1,  <Z2> = c0*c1*c2,  <Z3> = c0*c1*c2*c3
// FC(784->10) uses Blackwell fma.rn.f32x2 (2 classes per instruction).

#define G_IMGS 8
#define TPB    224        // 7 warps; threads [0,196) = 14x14 patches
#define NW     7
#define NP     5          // 10 classes as 5 packed pairs
#define PSTR   41         // 8 imgs * 5 pairs + 1 pad (odd stride, conflict-free)

typedef unsigned long long u64;

__device__ __forceinline__ u64 pack2(float lo, float hi) {
    u64 r; asm("mov.b64 %0,{%1,%2};" : "=l"(r) : "f"(lo), "f"(hi)); return r;
}
__device__ __forceinline__ void unpack2(u64 v, float& lo, float& hi) {
    asm("mov.b64 {%0,%1},%2;" : "=f"(lo), "=f"(hi) : "l"(v));
}
__device__ __forceinline__ u64 fma2(u64 a, u64 b, u64 c) {
    u64 d; asm("fma.rn.f32x2 %0,%1,%2,%3;" : "=l"(d) : "l"(a), "l"(b), "l"(c)); return d;
}
__device__ __forceinline__ u64 add2(u64 a, u64 b) {
    u64 d; asm("add.rn.f32x2 %0,%1,%2;" : "=l"(d) : "l"(a), "l"(b)); return d;
}

__global__ __launch_bounds__(TPB) void quanv_fused(
    const float* __restrict__ x,        // [B,1,28,28]
    const float* __restrict__ conv_w,   // [4,1,2,2]
    const float* __restrict__ conv_b,   // [4]
    const float* __restrict__ angles,   // [5]
    const float* __restrict__ fc_w,     // [10, 784]
    const float* __restrict__ fc_b,     // [10]
    float* __restrict__ out,            // [B,10]
    int B)
{
    const int t    = threadIdx.x;
    const int lane = t & 31;
    const int warp = t >> 5;
    const int b0   = blockIdx.x * G_IMGS;

    // s_part[warp][halfLane][g*5+opair] packed partial logit pairs
    __shared__ u64   s_part[NW][16][PSTR];
    __shared__ float s_logits[G_IMGS][10];

    // Uniform parameters (broadcast LDGs)
    float w00[4], w01[4], w10[4], w11[4], bb[4];
#pragma unroll
    for (int c = 0; c < 4; c++) {
        w00[c] = conv_w[c * 4 + 0];
        w01[c] = conv_w[c * 4 + 1];
        w10[c] = conv_w[c * 4 + 2];
        w11[c] = conv_w[c * 4 + 3];
        bb[c]  = conv_b[c] + angles[c];   // fold learned RY into encoding
    }
    float sa4, ca4;
    __sincosf(angles[4], &sa4, &ca4);

    const bool active = (t < 196);

    // Packed FC weights: fw2[c][j] = (fc_w[(2j)*784+c*196+t], fc_w[(2j+1)*784+c*196+t])
    u64 fw2[4][NP];
#pragma unroll
    for (int c = 0; c < 4; c++) {
#pragma unroll
        for (int j = 0; j < NP; j++) {
            float lo = active ? fc_w[(2 * j)     * 784 + c * 196 + t] : 0.0f;
            float hi = active ? fc_w[(2 * j + 1) * 784 + c * 196 + t] : 0.0f;
            fw2[c][j] = pack2(lo, hi);
        }
    }

    const int h    = t / 14;
    const int wq   = t - h * 14;
    const int poff = (2 * h) * 28 + 2 * wq;   // even -> 8B aligned float2
    const u64 zz   = pack2(0.0f, 0.0f);

#pragma unroll
    for (int g = 0; g < G_IMGS; g++) {
        u64 acc[NP];
#pragma unroll
        for (int j = 0; j < NP; j++) acc[j] = zz;

        const int b = b0 + g;
        if (active && b < B) {
            const float* xb = x + (size_t)b * 784 + poff;
            float2 p0 = *reinterpret_cast<const float2*>(xb);
            float2 p1 = *reinterpret_cast<const float2*>(xb + 28);

            float th[4];
#pragma unroll
            for (int c = 0; c < 4; c++)
                th[c] = fmaf(p0.x, w00[c],
                        fmaf(p0.y, w01[c],
                        fmaf(p1.x, w10[c],
                        fmaf(p1.y, w11[c], bb[c]))));

            float s0, c0, s1, c1;
            __sincosf(th[0], &s0, &c0);
            __sincosf(th[1], &s1, &c1);
            const float c2 = __cosf(th[2]);
            const float c3 = __cosf(th[3]);

            const float ez0 = fmaf(ca4, c0, -sa4 * s0 * s1);
            const float ez1 = c0 * c1;
            const float ez2 = ez1 * c2;
            const float ez3 = ez2 * c3;

            const u64 e0 = pack2(ez0, ez0);
            const u64 e1 = pack2(ez1, ez1);
            const u64 e2 = pack2(ez2, ez2);
            const u64 e3 = pack2(ez3, ez3);

#pragma unroll
            for (int j = 0; j < NP; j++)
                acc[j] = fma2(e0, fw2[0][j],
                         fma2(e1, fw2[1][j],
                         fma2(e2, fw2[2][j],
                         fma2(e3, fw2[3][j], zz))));
        }

        // 1-level reduce (lane += lane+16), packed adds
#pragma unroll
        for (int j = 0; j < NP; j++) {
            u64 other = __shfl_down_sync(0xffffffffu, acc[j], 16);
            acc[j] = add2(acc[j], other);
        }
        if (lane < 16) {
#pragma unroll
            for (int j = 0; j < NP; j++)
                s_part[warp][lane][g * NP + j] = acc[j];
        }
    }
    __syncthreads();

    // Tail: one thread per (image, class-pair): sums 7*16=112 packed partials
    if (t < G_IMGS * NP) {
        const int g = t / NP, j = t - g * NP;
        u64 v0 = pack2(fc_b[2 * j], fc_b[2 * j + 1]);
        u64 v1 = zz, v2 = zz, v3 = zz;
#pragma unroll
        for (int k = 0; k < NW; k++) {
#pragma unroll
            for (int i = 0; i < 16; i += 4) {
                v0 = add2(v0, s_part[k][i + 0][t]);
                v1 = add2(v1, s_part[k][i + 1][t]);
                v2 = add2(v2, s_part[k][i + 2][t]);
                v3 = add2(v3, s_part[k][i + 3][t]);
            }
        }
        u64 v = add2(add2(v0, v1), add2(v2, v3));
        float lo, hi; unpack2(v, lo, hi);
        s_logits[g][2 * j]     = lo;
        s_logits[g][2 * j + 1] = hi;
    }
    __syncthreads();

    // log_softmax over 10 classes
    if (t < G_IMGS * 10) {
        const int g = t / 10, o = t - g * 10;
        const int b = b0 + g;
        if (b < B) {
            float m = -1e30f;
#pragma unroll
            for (int j = 0; j < 10; j++) m = fmaxf(m, s_logits[g][j]);
            float se = 0.0f;
#pragma unroll
            for (int j = 0; j < 10; j++) se += __expf(s_logits[g][j] - m);
            out[b * 10 + o] = s_logits[g][o] - m - __logf(se);
        }
    }
}

extern "C" void kernel_launch(void* const* d_in, const int* in_sizes, int n_in,
                              void* d_out, int out_size)
{
    const float* x      = (const float*)d_in[0];
    const float* conv_w = (const float*)d_in[1];
    const float* conv_b = (const float*)d_in[2];
    const float* angles = (const float*)d_in[3];
    const float* fc_w   = (const float*)d_in[4];
    const float* fc_b   = (const float*)d_in[5];
    float* out = (float*)d_out;

    const int B = in_sizes[0] / 784;                 // 4096
    const int blocks = (B + G_IMGS - 1) / G_IMGS;    // 512

    quanv_fused<<<blocks, TPB>>>(x, conv_w, conv_b, angles, fc_w, fc_b, out, B);
}

// round 4
// speedup vs baseline: 1.7619x; 1.1756x over previous
#include <cuda_runtime.h>

// Fused Quanvolution-Hybrid (analytic 4-qubit circuit), f32x2 + 192-thread edition.
//   theta_w = conv_out_w + angles[w];  c_w=cos, s_w=sin
//   <Z0> = cos(a4)*c0 - sin(a4)*s0*s1
//   <Z1> = c0*c1,  <Z2> = c0*c1*c2,  <Z3> = c0*c1*c2*c3
// Patches 0..191 -> threads 1:1. Patches 192..195 x 8 images -> 32 lanes of warp 0.

#define G_IMGS 8
#define TPB    192        // 6 warps, all fully active
#define NW     6
#define NP     5          // 10 classes as 5 packed pairs
#define PSTR   41         // 8*5 + 1 pad (odd -> conflict-free strides)

typedef unsigned long long u64;

__device__ __forceinline__ u64 pack2(float lo, float hi) {
    u64 r; asm("mov.b64 %0,{%1,%2};" : "=l"(r) : "f"(lo), "f"(hi)); return r;
}
__device__ __forceinline__ void unpack2(u64 v, float& lo, float& hi) {
    asm("mov.b64 {%0,%1},%2;" : "=f"(lo), "=f"(hi) : "l"(v));
}
__device__ __forceinline__ u64 fma2(u64 a, u64 b, u64 c) {
    u64 d; asm("fma.rn.f32x2 %0,%1,%2,%3;" : "=l"(d) : "l"(a), "l"(b), "l"(c)); return d;
}
__device__ __forceinline__ u64 add2(u64 a, u64 b) {
    u64 d; asm("add.rn.f32x2 %0,%1,%2;" : "=l"(d) : "l"(a), "l"(b)); return d;
}

__global__ __launch_bounds__(TPB, 4) void quanv_fused(
    const float* __restrict__ x,        // [B,1,28,28]
    const float* __restrict__ conv_w,   // [4,1,2,2]
    const float* __restrict__ conv_b,   // [4]
    const float* __restrict__ angles,   // [5]
    const float* __restrict__ fc_w,     // [10, 784]
    const float* __restrict__ fc_b,     // [10]
    float* __restrict__ out,            // [B,10]
    int B)
{
    const int t    = threadIdx.x;
    const int lane = t & 31;
    const int warp = t >> 5;
    const int b0   = blockIdx.x * G_IMGS;

    __shared__ u64   s_part[NW][16][PSTR];     // main partial logit pairs
    __shared__ u64   s_extra[G_IMGS][4][NP];   // warp-0 epilogue partials [g][e][j]
    __shared__ u64   s_fwx[4][4][NP];          // fc weights for patches 192..195 [c][e][j]
    __shared__ float s_logits[G_IMGS][10];

    // ---- uniform parameters ----
    float w00[4], w01[4], w10[4], w11[4], bb[4];
#pragma unroll
    for (int c = 0; c < 4; c++) {
        w00[c] = conv_w[c * 4 + 0];
        w01[c] = conv_w[c * 4 + 1];
        w10[c] = conv_w[c * 4 + 2];
        w11[c] = conv_w[c * 4 + 3];
        bb[c]  = conv_b[c] + angles[c];   // fold learned RY into encoding
    }
    float sa4, ca4;
    __sincosf(angles[4], &sa4, &ca4);

    // ---- per-thread FC weight slice (patch t), packed pairs ----
    u64 fw2[4][NP];
#pragma unroll
    for (int c = 0; c < 4; c++) {
#pragma unroll
        for (int j = 0; j < NP; j++) {
            float lo = fc_w[(2 * j)     * 784 + c * 196 + t];
            float hi = fc_w[(2 * j + 1) * 784 + c * 196 + t];
            fw2[c][j] = pack2(lo, hi);
        }
    }

    // ---- extra-patch FC weights -> shared (80 pairs; threads 0..79) ----
    if (t < 80) {
        const int c  = t / 20;
        const int r  = t - c * 20;
        const int e  = r / NP;          // extra patch index 0..3 (patch 192+e)
        const int j  = r - e * NP;      // class pair
        const int pe = 192 + e;
        float lo = fc_w[(2 * j)     * 784 + c * 196 + pe];
        float hi = fc_w[(2 * j + 1) * 784 + c * 196 + pe];
        s_fwx[c][e][j] = pack2(lo, hi);
    }

    const int h    = t / 14;
    const int wq   = t - h * 14;
    const int poff = (2 * h) * 28 + 2 * wq;   // even -> 8B aligned float2
    const u64 zz   = pack2(0.0f, 0.0f);

    // ---- main loop: two halves of 4 images, loads front-batched ----
#pragma unroll
    for (int half = 0; half < 2; half++) {
        float2 p0[4], p1[4];
#pragma unroll
        for (int gg = 0; gg < 4; gg++) {
            const int b = b0 + half * 4 + gg;
            if (b < B) {
                const float* xb = x + (size_t)b * 784 + poff;
                p0[gg] = *reinterpret_cast<const float2*>(xb);
                p1[gg] = *reinterpret_cast<const float2*>(xb + 28);
            } else {
                p0[gg] = make_float2(0.f, 0.f);
                p1[gg] = make_float2(0.f, 0.f);
            }
        }

#pragma unroll
        for (int gg = 0; gg < 4; gg++) {
            const int g = half * 4 + gg;
            float th[4];
#pragma unroll
            for (int c = 0; c < 4; c++)
                th[c] = fmaf(p0[gg].x, w00[c],
                        fmaf(p0[gg].y, w01[c],
                        fmaf(p1[gg].x, w10[c],
                        fmaf(p1[gg].y, w11[c], bb[c]))));

            float s0, c0, s1, c1;
            __sincosf(th[0], &s0, &c0);
            __sincosf(th[1], &s1, &c1);
            const float c2 = __cosf(th[2]);
            const float c3 = __cosf(th[3]);

            const float ez0 = fmaf(ca4, c0, -sa4 * s0 * s1);
            const float ez1 = c0 * c1;
            const float ez2 = ez1 * c2;
            const float ez3 = ez2 * c3;

            const u64 e0 = pack2(ez0, ez0);
            const u64 e1 = pack2(ez1, ez1);
            const u64 e2 = pack2(ez2, ez2);
            const u64 e3 = pack2(ez3, ez3);

            u64 acc[NP];
            const bool ok = (b0 + g < B);
#pragma unroll
            for (int j = 0; j < NP; j++) {
                acc[j] = ok ? fma2(e0, fw2[0][j],
                              fma2(e1, fw2[1][j],
                              fma2(e2, fw2[2][j],
                              fma2(e3, fw2[3][j], zz)))) : zz;
            }

            // 1-level reduce (lane += lane+16), packed
#pragma unroll
            for (int j = 0; j < NP; j++) {
                u64 other = __shfl_down_sync(0xffffffffu, acc[j], 16);
                acc[j] = add2(acc[j], other);
            }
            if (lane < 16) {
#pragma unroll
                for (int j = 0; j < NP; j++)
                    s_part[warp][lane][g * NP + j] = acc[j];
            }
        }
    }

    // ---- warp-0 epilogue: patches 192..195 x 8 images, one per lane ----
    if (warp == 0) {
        const int e  = lane & 3;        // extra patch 192+e -> (h=13, w=10+e)
        const int ge = lane >> 2;       // image index
        const int b  = b0 + ge;
        u64 accx[NP];
        if (b < B) {
            const int pox = 26 * 28 + 2 * (10 + e);
            const float* xb = x + (size_t)b * 784 + pox;
            float2 q0 = *reinterpret_cast<const float2*>(xb);
            float2 q1 = *reinterpret_cast<const float2*>(xb + 28);

            float th[4];
#pragma unroll
            for (int c = 0; c < 4; c++)
                th[c] = fmaf(q0.x, w00[c],
                        fmaf(q0.y, w01[c],
                        fmaf(q1.x, w10[c],
                        fmaf(q1.y, w11[c], bb[c]))));

            float s0, c0, s1, c1;
            __sincosf(th[0], &s0, &c0);
            __sincosf(th[1], &s1, &c1);
            const float c2 = __cosf(th[2]);
            const float c3 = __cosf(th[3]);

            const float ez0 = fmaf(ca4, c0, -sa4 * s0 * s1);
            const float ez1 = c0 * c1;
            const float ez2 = ez1 * c2;
            const float ez3 = ez2 * c3;

            const u64 e0p = pack2(ez0, ez0);
            const u64 e1p = pack2(ez1, ez1);
            const u64 e2p = pack2(ez2, ez2);
            const u64 e3p = pack2(ez3, ez3);
#pragma unroll
            for (int j = 0; j < NP; j++)
                accx[j] = fma2(e0p, s_fwx[0][e][j],
                          fma2(e1p, s_fwx[1][e][j],
                          fma2(e2p, s_fwx[2][e][j],
                          fma2(e3p, s_fwx[3][e][j], zz))));
        } else {
#pragma unroll
            for (int j = 0; j < NP; j++) accx[j] = zz;
        }
#pragma unroll
        for (int j = 0; j < NP; j++)
            s_extra[ge][e][j] = accx[j];
    }
    __syncthreads();

    // ---- tail: one thread per (image, class-pair) ----
    if (t < G_IMGS * NP) {
        const int g = t / NP, j = t - g * NP;
        u64 v0 = pack2(fc_b[2 * j], fc_b[2 * j + 1]);
        u64 v1 = zz, v2 = zz, v3 = zz;
#pragma unroll
        for (int k = 0; k < NW; k++) {
#pragma unroll
            for (int i = 0; i < 16; i += 4) {
                v0 = add2(v0, s_part[k][i + 0][t]);
                v1 = add2(v1, s_part[k][i + 1][t]);
                v2 = add2(v2, s_part[k][i + 2][t]);
                v3 = add2(v3, s_part[k][i + 3][t]);
            }
        }
#pragma unroll
        for (int e = 0; e < 4; e++)
            v0 = add2(v0, s_extra[g][e][j]);
        u64 v = add2(add2(v0, v1), add2(v2, v3));
        float lo, hi; unpack2(v, lo, hi);
        s_logits[g][2 * j]     = lo;
        s_logits[g][2 * j + 1] = hi;
    }
    __syncthreads();

    // ---- log_softmax over 10 classes ----
    if (t < G_IMGS * 10) {
        const int g = t / 10, o = t - g * 10;
        const int b = b0 + g;
        if (b < B) {
            float m = -1e30f;
#pragma unroll
            for (int j = 0; j < 10; j++) m = fmaxf(m, s_logits[g][j]);
            float se = 0.0f;
#pragma unroll
            for (int j = 0; j < 10; j++) se += __expf(s_logits[g][j] - m);
            out[b * 10 + o] = s_logits[g][o] - m - __logf(se);
        }
    }
}

extern "C" void kernel_launch(void* const* d_in, const int* in_sizes, int n_in,
                              void* d_out, int out_size)
{
    const float* x      = (const float*)d_in[0];
    const float* conv_w = (const float*)d_in[1];
    const float* conv_b = (const float*)d_in[2];
    const float* angles = (const float*)d_in[3];
    const float* fc_w   = (const float*)d_in[4];
    const float* fc_b   = (const float*)d_in[5];
    float* out = (float*)d_out;

    const int B = in_sizes[0] / 784;                 // 4096
    const int blocks = (B + G_IMGS - 1) / G_IMGS;    // 512

    quanv_fused<<<blocks, TPB>>>(x, conv_w, conv_b, angles, fc_w, fc_b, out, B);
}